// round 13
// baseline (speedup 1.0000x reference)
#include <cuda_runtime.h>
#include <cuda_fp16.h>
#include <cstdint>

#define BSZ 16384
#define EDIM 1024
#define TDIM 768

// ---------------- scratch (__device__ globals; allocation is forbidden) ----------------
__device__ __half g_t_h[(size_t)BSZ * EDIM];
__device__ __half g_a_h[(size_t)BSZ * EDIM];
__device__ __half g_tctx_h[(size_t)BSZ * EDIM];
__device__ __half g_actx_h[(size_t)BSZ * EDIM];
__device__ __half g_text_h[(size_t)BSZ * TDIM];
__device__ __half g_aud_h[(size_t)BSZ * EDIM];
__device__ __half g_Wt_h[(size_t)EDIM * TDIM];
__device__ __half g_Wa_h[(size_t)EDIM * EDIM];
__device__ __half g_Wgt_h[(size_t)EDIM * 2 * EDIM];
__device__ __half g_Wga_h[(size_t)EDIM * 2 * EDIM];
__device__ __half g_Wo_h[(size_t)EDIM * EDIM];
__device__ __half g_WvT_h[(size_t)EDIM * EDIM];
__device__ __half g_Wvo_h[(size_t)EDIM * EDIM];
__device__ float g_bvo[EDIM];

// ---------------- helpers ----------------
static __device__ __forceinline__ uint32_t s2u(const void* p) {
    uint32_t a;
    asm("{ .reg .u64 t; cvta.to.shared.u64 t, %1; cvt.u32.u64 %0, t; }" : "=r"(a) : "l"(p));
    return a;
}
static __device__ __forceinline__ void cpa16(uint32_t d, const void* s) {
    asm volatile("cp.async.cg.shared.global [%0], [%1], 16;" :: "r"(d), "l"(s));
}
static __device__ __forceinline__ void ldsm4(uint32_t* r, uint32_t addr) {
    asm volatile("ldmatrix.sync.aligned.m8n8.x4.shared.b16 {%0,%1,%2,%3}, [%4];"
                 : "=r"(r[0]), "=r"(r[1]), "=r"(r[2]), "=r"(r[3]) : "r"(addr));
}
static __device__ __forceinline__ void mma16816(float* c, const uint32_t* a, uint32_t b0, uint32_t b1) {
    asm volatile(
        "mma.sync.aligned.m16n8k16.row.col.f32.f16.f16.f32 "
        "{%0,%1,%2,%3}, {%4,%5,%6,%7}, {%8,%9}, {%0,%1,%2,%3};"
        : "+f"(c[0]), "+f"(c[1]), "+f"(c[2]), "+f"(c[3])
        : "r"(a[0]), "r"(a[1]), "r"(a[2]), "r"(a[3]), "r"(b0), "r"(b1));
}
// ---- mbarrier primitives (plain sm_90 PTX; no arch-suffix features) ----
static __device__ __forceinline__ void mbar_init(uint32_t a, uint32_t cnt) {
    asm volatile("mbarrier.init.shared.b64 [%0], %1;" :: "r"(a), "r"(cnt) : "memory");
}
static __device__ __forceinline__ void mbar_arrive(uint32_t a) {
    asm volatile("mbarrier.arrive.shared.b64 _, [%0];" :: "r"(a) : "memory");
}
static __device__ __forceinline__ void cpa_mbar_arrive(uint32_t a) {
    asm volatile("cp.async.mbarrier.arrive.noinc.shared.b64 [%0];" :: "r"(a) : "memory");
}
static __device__ __forceinline__ void mbar_wait(uint32_t a, uint32_t parity) {
    asm volatile(
        "{\n\t.reg .pred P1;\n\t"
        "LAB_%=:\n\t"
        "mbarrier.try_wait.parity.acquire.cta.shared::cta.b64 P1, [%0], %1, 0x989680;\n\t"
        "@P1 bra.uni DONE_%=;\n\t"
        "bra.uni LAB_%=;\n\t"
        "DONE_%=:\n\t}"
        :: "r"(a), "r"(parity) : "memory");
}

// ---------------- SMEM layout ----------------
// [0..40)    full[5] mbarriers  (128 arrivals: loader threads 0..127, cp-async tracked)
// [40..80)   empty[5] mbarriers (8 arrivals: lane 0 of each warp post-compute)
// [1024..)   5 stages x 20480 B (A 128x80 + B 128x80, 80 B row pad = conflict-free ldmatrix)
// Total 103424 B/CTA; 2 CTAs/SM = 206848 <= 228 KB.
// mbarrier ring, issue distance 3; loading confined to threads 0..127 (one full
// A row + one full B row each: 8 cp.async + 1 tracked arrive); warps 4-7 run a
// pure wait/compute/arrive loop. No __syncthreads in the mainloop.
#define A_BYTES 10240
#define STAGE_BYTES 20480
#define SM_STAGE0 1024
#define SMEM_BYTES (1024 + 5 * STAGE_BYTES)

struct GArgs {
    const __half* A0; const __half* A1; const __half* W;
    const float* bias; float* Cf; __half* Ch;
    const __half* X; const __half* Xc;
    int lda, ldw, K, Ksplit;
};

// C[row, col] = sum_k A[row, k] * W[col, k] (+ bias[col]); A switches A0->A1 at
// k = Ksplit (concat-free gate). GATE: fused sigmoid blend -> Cf (f32).
// !GATE: emits Ch (f16) only.  SMALLZ2: z == 2 lane only covers blockIdx.y < 8
// (the 1024x1024 Wvo GEMM piggybacking on the projections launch).
template <bool GATE, bool SMALLZ2>
__global__ __launch_bounds__(256, 2) void hgemm(GArgs ga, GArgs gb, GArgs gc)
{
    if (SMALLZ2 && blockIdx.z == 2 && blockIdx.y >= 8) return;
    const GArgs g = (blockIdx.z == 0) ? ga : (blockIdx.z == 1 ? gb : gc);
    extern __shared__ __align__(16) char smem[];
    const uint32_t sb = s2u(smem);
    const int tid  = threadIdx.x;
    const int warp = tid >> 5;
    const int lane = tid & 31;
    const int bm = blockIdx.y * 128;
    const int bn = blockIdx.x * 128;
    const int wm = (warp & 1) * 64;    // warp grid 2(m) x 4(n), warp tile 64x32
    const int wn = (warp >> 1) * 32;
    const int T = g.K / 32;
    const bool loader = (tid < 128);

    if (tid == 0) {
#pragma unroll
        for (int s = 0; s < 5; s++) {
            mbar_init(sb + s * 8, 128);        // full[s]: 128 loader arrivals
            mbar_init(sb + 40 + s * 8, 8);     // empty[s]: 8 per-warp arrivals
        }
    }
    __syncthreads();

    // loader thread i (0..127): A row i (4 x 16B) + B row i (4 x 16B)
    auto issue = [&](int ti) {
        const int s = ti % 5;
        const int k0 = ti * 32;
        const __half* Ap; int kk;
        if (k0 < g.Ksplit) { Ap = g.A0; kk = k0; }
        else               { Ap = g.A1; kk = k0 - g.Ksplit; }
        const __half* srcA = Ap + (size_t)(bm + tid) * g.lda + kk;
        const uint32_t dA = sb + SM_STAGE0 + s * STAGE_BYTES + tid * 80;
#pragma unroll
        for (int j = 0; j < 4; j++) cpa16(dA + j * 16, srcA + j * 8);
        const __half* srcB = g.W + (size_t)(bn + tid) * g.ldw + k0;
        const uint32_t dB = sb + SM_STAGE0 + s * STAGE_BYTES + A_BYTES + tid * 80;
#pragma unroll
        for (int j = 0; j < 4; j++) cpa16(dB + j * 16, srcB + j * 8);
        cpa_mbar_arrive(sb + s * 8);           // fires when this thread's 8 loads land
    };

    const uint32_t aoff = (uint32_t)(wm + (lane & 15)) * 80 + (lane >> 4) * 16;
    const uint32_t boff = (uint32_t)(wn + ((lane >> 4) & 1) * 8 + (lane & 7)) * 80 +
                          ((lane >> 3) & 1) * 16;

    float acc[4][4][4];
#pragma unroll
    for (int i = 0; i < 4; i++)
#pragma unroll
        for (int j = 0; j < 4; j++)
#pragma unroll
            for (int q = 0; q < 4; q++) acc[i][j][q] = 0.f;

    auto compute = [&](int ti) {
        const uint32_t sA = sb + SM_STAGE0 + (ti % 5) * STAGE_BYTES;
        const uint32_t sB = sA + A_BYTES;
#pragma unroll
        for (int ks = 0; ks < 2; ks++) {
            uint32_t ar[4][4], br[2][4];
#pragma unroll
            for (int mi = 0; mi < 4; mi++)
                ldsm4(ar[mi], sA + aoff + mi * (16 * 80) + ks * 32);
#pragma unroll
            for (int nj = 0; nj < 2; nj++)
                ldsm4(br[nj], sB + boff + nj * (16 * 80) + ks * 32);
#pragma unroll
            for (int mi = 0; mi < 4; mi++)
#pragma unroll
                for (int ni = 0; ni < 4; ni++)
                    mma16816(acc[mi][ni], ar[mi],
                             br[ni >> 1][(ni & 1) * 2], br[ni >> 1][(ni & 1) * 2 + 1]);
        }
    };

    if (loader) { issue(0); issue(1); issue(2); }

    for (int t = 0; t < T; t++) {
        const int ti = t + 3;
        if (loader && ti < T) {
            const int s3 = ti % 5;
            if (ti >= 5) mbar_wait(sb + 40 + s3 * 8, ((ti / 5) - 1) & 1);  // empty[s3]
            issue(ti);
        }
        mbar_wait(sb + (t % 5) * 8, (t / 5) & 1);                          // full[t%5]
        compute(t);
        if (lane == 0) mbar_arrive(sb + 40 + (t % 5) * 8);                 // empty[t%5], per-warp
    }

    // ---- epilogue: direct register -> global, fused bias (+ sigmoid blend)
    const int lane4 = lane >> 2;
    const int lanec = (lane & 3) * 2;
#pragma unroll
    for (int mi = 0; mi < 4; mi++) {
#pragma unroll
        for (int hf = 0; hf < 2; hf++) {
            const int r = bm + wm + mi * 16 + lane4 + hf * 8;
            const size_t rowE = (size_t)r * EDIM;
#pragma unroll
            for (int ni = 0; ni < 4; ni++) {
                const int c = bn + wn + ni * 8 + lanec;
                float v0 = acc[mi][ni][hf * 2 + 0];
                float v1 = acc[mi][ni][hf * 2 + 1];
                if (g.bias) {
                    float2 bb = *(const float2*)(g.bias + c);
                    v0 += bb.x; v1 += bb.y;
                }
                if (GATE) {
                    __half2 xh = *(const __half2*)(g.X + rowE + c);
                    __half2 ch = *(const __half2*)(g.Xc + rowE + c);
                    float x0 = __low2float(xh), x1 = __high2float(xh);
                    float c0 = __low2float(ch), c1 = __high2float(ch);
                    float s0 = 1.f / (1.f + __expf(-v0));
                    float s1 = 1.f / (1.f + __expf(-v1));
                    float2 o;
                    o.x = s0 * x0 + (1.f - s0) * c0;
                    o.y = s1 * x1 + (1.f - s1) * c1;
                    *(float2*)(g.Cf + rowE + c) = o;
                } else {
                    *(__half2*)(g.Ch + rowE + c) = __floats2half2_rn(v0, v1);
                }
            }
        }
    }
}

// ---------------- fused fp32 -> fp16 conversion (all 7 tensors, one launch) ----------------
#define N4_TEXT ((size_t)BSZ * TDIM / 4)
#define N4_AUD  ((size_t)BSZ * EDIM / 4)
#define N4_WT   ((size_t)EDIM * TDIM / 4)
#define N4_WA   ((size_t)EDIM * EDIM / 4)
#define N4_WG   ((size_t)EDIM * 2 * EDIM / 4)
#define C0 (N4_TEXT)
#define C1 (C0 + N4_AUD)
#define C2 (C1 + N4_WT)
#define C3 (C2 + N4_WA)
#define C4 (C3 + N4_WG)
#define C5 (C4 + N4_WG)
#define C6 (C5 + N4_WA)

struct CvtArgs {
    const float* s0; const float* s1; const float* s2; const float* s3;
    const float* s4; const float* s5; const float* s6;
    __half *d0, *d1, *d2, *d3, *d4, *d5, *d6;
};

__global__ void cvt_all_kernel(CvtArgs a) {
    size_t i = (size_t)blockIdx.x * blockDim.x + threadIdx.x;
    if (i >= C6) return;
    const float* src; __half* dst; size_t off;
    if      (i < C0) { src = a.s0; dst = a.d0; off = i; }
    else if (i < C1) { src = a.s1; dst = a.d1; off = i - C0; }
    else if (i < C2) { src = a.s2; dst = a.d2; off = i - C1; }
    else if (i < C3) { src = a.s3; dst = a.d3; off = i - C2; }
    else if (i < C4) { src = a.s4; dst = a.d4; off = i - C3; }
    else if (i < C5) { src = a.s5; dst = a.d5; off = i - C4; }
    else             { src = a.s6; dst = a.d6; off = i - C5; }
    float4 v = ((const float4*)src)[off];
    __half2 h0 = __floats2half2_rn(v.x, v.y);
    __half2 h1 = __floats2half2_rn(v.z, v.w);
    uint2 u; u.x = *(uint32_t*)&h0; u.y = *(uint32_t*)&h1;
    ((uint2*)dst)[off] = u;
}

__global__ void transpose_cvt1024(const float* __restrict__ in, __half* __restrict__ out) {
    __shared__ float tile[32][33];
    int x = blockIdx.x * 32 + threadIdx.x;
    int y = blockIdx.y * 32 + threadIdx.y;
#pragma unroll
    for (int i = 0; i < 32; i += 8)
        tile[threadIdx.y + i][threadIdx.x] = in[(size_t)(y + i) * EDIM + x];
    __syncthreads();
    x = blockIdx.y * 32 + threadIdx.x;
    y = blockIdx.x * 32 + threadIdx.y;
#pragma unroll
    for (int i = 0; i < 32; i += 8)
        out[(size_t)(y + i) * EDIM + x] = __float2half_rn(tile[threadIdx.x][threadIdx.y + i]);
}

__global__ void bvo_kernel(const float* __restrict__ Wo, const float* __restrict__ bv,
                           const float* __restrict__ bo, float* __restrict__ bvo) {
    int n = blockIdx.x * (blockDim.x >> 5) + (threadIdx.x >> 5);
    int lane = threadIdx.x & 31;
    const float* row = Wo + (size_t)n * EDIM;
    float s = 0.f;
    for (int k = lane; k < EDIM; k += 32) s += row[k] * bv[k];
#pragma unroll
    for (int off = 16; off; off >>= 1) s += __shfl_xor_sync(0xFFFFFFFFu, s, off);
    if (lane == 0) bvo[n] = s + bo[n];
}

// ---------------- launch ----------------
extern "C" void kernel_launch(void* const* d_in, const int* in_sizes, int n_in,
                              void* d_out, int out_size)
{
    const float* text  = (const float*)d_in[0];
    const float* audio = (const float*)d_in[1];
    const float* Wt  = (const float*)d_in[2];
    const float* bt  = (const float*)d_in[3];
    const float* Wa  = (const float*)d_in[4];
    const float* ba  = (const float*)d_in[5];
    // d_in[6..9] = Wq,bq,Wk,bk : dead (softmax over length-1 kv axis == 1 -> ctx == v)
    const float* Wv  = (const float*)d_in[10];
    const float* bv  = (const float*)d_in[11];
    const float* Wo  = (const float*)d_in[12];
    const float* bo  = (const float*)d_in[13];
    const float* Wgt = (const float*)d_in[14];
    const float* bgt = (const float*)d_in[15];
    const float* Wga = (const float*)d_in[16];
    const float* bga = (const float*)d_in[17];
    float* out = (float*)d_out;

    float *bvo;
    __half *t_h, *a_h, *tctx_h, *actx_h, *text_h, *aud_h;
    __half *Wt_h, *Wa_h, *Wgt_h, *Wga_h, *Wo_h, *WvT_h, *Wvo_h;
    cudaGetSymbolAddress((void**)&t_h, g_t_h);       cudaGetSymbolAddress((void**)&a_h, g_a_h);
    cudaGetSymbolAddress((void**)&tctx_h, g_tctx_h); cudaGetSymbolAddress((void**)&actx_h, g_actx_h);
    cudaGetSymbolAddress((void**)&text_h, g_text_h); cudaGetSymbolAddress((void**)&aud_h, g_aud_h);
    cudaGetSymbolAddress((void**)&Wt_h, g_Wt_h);     cudaGetSymbolAddress((void**)&Wa_h, g_Wa_h);
    cudaGetSymbolAddress((void**)&Wgt_h, g_Wgt_h);   cudaGetSymbolAddress((void**)&Wga_h, g_Wga_h);
    cudaGetSymbolAddress((void**)&Wo_h, g_Wo_h);     cudaGetSymbolAddress((void**)&WvT_h, g_WvT_h);
    cudaGetSymbolAddress((void**)&Wvo_h, g_Wvo_h);   cudaGetSymbolAddress((void**)&bvo, g_bvo);

    cudaFuncSetAttribute(hgemm<false, true>,  cudaFuncAttributeMaxDynamicSharedMemorySize, SMEM_BYTES);
    cudaFuncSetAttribute(hgemm<false, false>, cudaFuncAttributeMaxDynamicSharedMemorySize, SMEM_BYTES);
    cudaFuncSetAttribute(hgemm<true, false>,  cudaFuncAttributeMaxDynamicSharedMemorySize, SMEM_BYTES);

    // fused fp16 operand prep (one launch for all 7 tensors)
    {
        CvtArgs ca = { text, audio, Wt, Wa, Wgt, Wga, Wo,
                       text_h, aud_h, Wt_h, Wa_h, Wgt_h, Wga_h, Wo_h };
        cvt_all_kernel<<<(unsigned)((C6 + 255) / 256), 256>>>(ca);
    }
    transpose_cvt1024<<<dim3(32, 32), dim3(32, 8)>>>(Wv, WvT_h);
    bvo_kernel<<<EDIM / 8, 256>>>(Wo, bv, bo, bvo);

    const dim3 blk(256);

    // projections + Wvo in one launch:
    //   z=0: t = text@Wt^T + bt ; z=1: a = audio@Wa^T + ba ; z=2 (y<8): Wvo = Wo@Wv
    {
        GArgs gt  = { text_h, text_h, Wt_h, bt, nullptr, t_h, nullptr, nullptr,
                      TDIM, TDIM, TDIM, TDIM };
        GArgs gaa = { aud_h, aud_h, Wa_h, ba, nullptr, a_h, nullptr, nullptr,
                      EDIM, EDIM, EDIM, EDIM };
        GArgs gw  = { Wo_h, Wo_h, WvT_h, nullptr, nullptr, Wvo_h, nullptr, nullptr,
                      EDIM, EDIM, EDIM, EDIM };
        hgemm<false, true><<<dim3(8, 128, 3), blk, SMEM_BYTES>>>(gt, gaa, gw);
    }
    // contexts (attention collapsed to V-then-O): tctx = a@Wvo^T + bvo ; actx = t@Wvo^T + bvo
    {
        GArgs g0 = { a_h, a_h, Wvo_h, bvo, nullptr, tctx_h, nullptr, nullptr,
                     EDIM, EDIM, EDIM, EDIM };
        GArgs g1 = { t_h, t_h, Wvo_h, bvo, nullptr, actx_h, nullptr, nullptr,
                     EDIM, EDIM, EDIM, EDIM };
        hgemm<false, false><<<dim3(8, 128, 2), blk, SMEM_BYTES>>>(g0, g1, g0);
    }
    // gates: K = 2048, A switches x -> ctx at k = 1024; fused sigmoid blend
    {
        GArgs g0 = { t_h, tctx_h, Wgt_h, bgt, out, nullptr, t_h, tctx_h,
                     EDIM, 2 * EDIM, 2 * EDIM, EDIM };
        GArgs g1 = { a_h, actx_h, Wga_h, bga, out + (size_t)BSZ * EDIM, nullptr, a_h, actx_h,
                     EDIM, 2 * EDIM, 2 * EDIM, EDIM };
        hgemm<true, false><<<dim3(8, 128, 2), blk, SMEM_BYTES>>>(g0, g1, g0);
    }
}

// round 14
// speedup vs baseline: 1.4415x; 1.4415x over previous
#include <cuda_runtime.h>
#include <cuda_fp16.h>
#include <cstdint>

#define BSZ 16384
#define EDIM 1024
#define TDIM 768

// ---------------- scratch (__device__ globals; allocation is forbidden) ----------------
__device__ __half g_t_h[(size_t)BSZ * EDIM];
__device__ __half g_a_h[(size_t)BSZ * EDIM];
__device__ __half g_tctx_h[(size_t)BSZ * EDIM];
__device__ __half g_actx_h[(size_t)BSZ * EDIM];
__device__ __half g_text_h[(size_t)BSZ * TDIM];
__device__ __half g_aud_h[(size_t)BSZ * EDIM];
__device__ __half g_Wt_h[(size_t)EDIM * TDIM];
__device__ __half g_Wa_h[(size_t)EDIM * EDIM];
__device__ __half g_Wgt_h[(size_t)EDIM * 2 * EDIM];
__device__ __half g_Wga_h[(size_t)EDIM * 2 * EDIM];
__device__ __half g_Wo_h[(size_t)EDIM * EDIM];
__device__ __half g_WvT_h[(size_t)EDIM * EDIM];
__device__ __half g_Wvo_h[(size_t)EDIM * EDIM];
__device__ float g_bvo[EDIM];

// ---------------- helpers ----------------
static __device__ __forceinline__ uint32_t s2u(const void* p) {
    uint32_t a;
    asm("{ .reg .u64 t; cvta.to.shared.u64 t, %1; cvt.u32.u64 %0, t; }" : "=r"(a) : "l"(p));
    return a;
}
static __device__ __forceinline__ void cpa16(uint32_t d, const void* s) {
    asm volatile("cp.async.cg.shared.global [%0], [%1], 16;" :: "r"(d), "l"(s));
}
static __device__ __forceinline__ void ldsm4(uint32_t* r, uint32_t addr) {
    asm volatile("ldmatrix.sync.aligned.m8n8.x4.shared.b16 {%0,%1,%2,%3}, [%4];"
                 : "=r"(r[0]), "=r"(r[1]), "=r"(r[2]), "=r"(r[3]) : "r"(addr));
}
static __device__ __forceinline__ void mma16816(float* c, const uint32_t* a, uint32_t b0, uint32_t b1) {
    asm volatile(
        "mma.sync.aligned.m16n8k16.row.col.f32.f16.f16.f32 "
        "{%0,%1,%2,%3}, {%4,%5,%6,%7}, {%8,%9}, {%0,%1,%2,%3};"
        : "+f"(c[0]), "+f"(c[1]), "+f"(c[2]), "+f"(c[3])
        : "r"(a[0]), "r"(a[1]), "r"(a[2]), "r"(a[3]), "r"(b0), "r"(b1));
}
// ---- mbarrier primitives (plain sm_90 PTX; no arch-suffix features) ----
static __device__ __forceinline__ void mbar_init(uint32_t a, uint32_t cnt) {
    asm volatile("mbarrier.init.shared.b64 [%0], %1;" :: "r"(a), "r"(cnt) : "memory");
}
static __device__ __forceinline__ void mbar_arrive(uint32_t a) {
    asm volatile("mbarrier.arrive.shared.b64 _, [%0];" :: "r"(a) : "memory");
}
static __device__ __forceinline__ void cpa_mbar_arrive(uint32_t a) {
    asm volatile("cp.async.mbarrier.arrive.noinc.shared.b64 [%0];" :: "r"(a) : "memory");
}
static __device__ __forceinline__ void mbar_wait(uint32_t a, uint32_t parity) {
    asm volatile(
        "{\n\t.reg .pred P1;\n\t"
        "LAB_%=:\n\t"
        "mbarrier.try_wait.parity.acquire.cta.shared::cta.b64 P1, [%0], %1, 0x989680;\n\t"
        "@P1 bra.uni DONE_%=;\n\t"
        "bra.uni LAB_%=;\n\t"
        "DONE_%=:\n\t}"
        :: "r"(a), "r"(parity) : "memory");
}

// ---------------- SMEM layout ----------------
// [0..40)    full[5] mbarriers  (256 arrivals: every thread's cp-async tracked arrive)
// [40..80)   empty[5] mbarriers (8 arrivals: lane 0 of each warp, early-arrive after ldsm)
// [1024..)   5 stages x 20480 B (A 128x80 + B 128x80, 80 B row pad = conflict-free ldmatrix)
// Total 103424 B/CTA; 2 CTAs/SM = 206848 <= 228 KB.
// mbarrier ring, issue distance 3, loads balanced across all 256 threads
// (R13's loader-split regression reverted). No __syncthreads in the mainloop.
#define A_BYTES 10240
#define STAGE_BYTES 20480
#define SM_STAGE0 1024
#define SMEM_BYTES (1024 + 5 * STAGE_BYTES)

struct GArgs {
    const __half* A0; const __half* A1; const __half* W;
    const float* bias; float* Cf; __half* Ch;
    const __half* X; const __half* Xc;
    int lda, ldw, K, Ksplit;
};

// C[row, col] = sum_k A[row, k] * W[col, k] (+ bias[col]); A switches A0->A1 at
// k = Ksplit (concat-free gate). GATE: fused sigmoid blend -> Cf (f32).
// !GATE: emits Ch (f16) only.  SMALLZ2: z == 2 lane only covers blockIdx.y < 8
// (the 1024x1024 Wvo GEMM piggybacking on the projections launch).
template <bool GATE, bool SMALLZ2>
__global__ __launch_bounds__(256, 2) void hgemm(GArgs ga, GArgs gb, GArgs gc)
{
    if (SMALLZ2 && blockIdx.z == 2 && blockIdx.y >= 8) return;
    const GArgs g = (blockIdx.z == 0) ? ga : (blockIdx.z == 1 ? gb : gc);
    extern __shared__ __align__(16) char smem[];
    const uint32_t sb = s2u(smem);
    const int tid  = threadIdx.x;
    const int warp = tid >> 5;
    const int lane = tid & 31;
    const int bm = blockIdx.y * 128;
    const int bn = blockIdx.x * 128;
    const int wm = (warp & 1) * 64;    // warp grid 2(m) x 4(n), warp tile 64x32
    const int wn = (warp >> 1) * 32;
    const int T = g.K / 32;

    const int rowL = tid >> 1;
    const int cL = (tid & 1) * 2;      // 16B units

    if (tid == 0) {
#pragma unroll
        for (int s = 0; s < 5; s++) {
            mbar_init(sb + s * 8, 256);        // full[s]: all-thread cp-async arrivals
            mbar_init(sb + 40 + s * 8, 8);     // empty[s]: lane-0-per-warp arrivals
        }
    }
    __syncthreads();

    auto issue = [&](int ti) {
        const int s = ti % 5;
        const int k0 = ti * 32;
        const __half* Ap; int kk;
        if (k0 < g.Ksplit) { Ap = g.A0; kk = k0; }
        else               { Ap = g.A1; kk = k0 - g.Ksplit; }
        const __half* srcA = Ap + (size_t)(bm + rowL) * g.lda + kk + cL * 8;
        const uint32_t dA = sb + SM_STAGE0 + s * STAGE_BYTES + rowL * 80 + cL * 16;
        cpa16(dA, srcA); cpa16(dA + 16, srcA + 8);
        const __half* srcB = g.W + (size_t)(bn + rowL) * g.ldw + k0 + cL * 8;
        const uint32_t dB = sb + SM_STAGE0 + s * STAGE_BYTES + A_BYTES + rowL * 80 + cL * 16;
        cpa16(dB, srcB); cpa16(dB + 16, srcB + 8);
        cpa_mbar_arrive(sb + s * 8);           // arrive full[s] when these loads land
    };

    const uint32_t aoff = (uint32_t)(wm + (lane & 15)) * 80 + (lane >> 4) * 16;
    const uint32_t boff = (uint32_t)(wn + ((lane >> 4) & 1) * 8 + (lane & 7)) * 80 +
                          ((lane >> 3) & 1) * 16;

    float acc[4][4][4];
#pragma unroll
    for (int i = 0; i < 4; i++)
#pragma unroll
        for (int j = 0; j < 4; j++)
#pragma unroll
            for (int q = 0; q < 4; q++) acc[i][j][q] = 0.f;

    // compute(t): ks=0 ldsm+mma; ks=1 ldsm, then EARLY empty-arrive (stage smem no
    // longer needed once fragments are in registers), then ks=1 mma.
    auto compute = [&](int ti, uint32_t emptyAddr) {
        const uint32_t sA = sb + SM_STAGE0 + (ti % 5) * STAGE_BYTES;
        const uint32_t sB = sA + A_BYTES;
        {
            uint32_t ar[4][4], br[2][4];
#pragma unroll
            for (int mi = 0; mi < 4; mi++)
                ldsm4(ar[mi], sA + aoff + mi * (16 * 80));
#pragma unroll
            for (int nj = 0; nj < 2; nj++)
                ldsm4(br[nj], sB + boff + nj * (16 * 80));
#pragma unroll
            for (int mi = 0; mi < 4; mi++)
#pragma unroll
                for (int ni = 0; ni < 4; ni++)
                    mma16816(acc[mi][ni], ar[mi],
                             br[ni >> 1][(ni & 1) * 2], br[ni >> 1][(ni & 1) * 2 + 1]);
        }
        {
            uint32_t ar[4][4], br[2][4];
#pragma unroll
            for (int mi = 0; mi < 4; mi++)
                ldsm4(ar[mi], sA + aoff + mi * (16 * 80) + 32);
#pragma unroll
            for (int nj = 0; nj < 2; nj++)
                ldsm4(br[nj], sB + boff + nj * (16 * 80) + 32);
            if (lane == 0) mbar_arrive(emptyAddr);   // stage fully consumed (regs hold data)
#pragma unroll
            for (int mi = 0; mi < 4; mi++)
#pragma unroll
                for (int ni = 0; ni < 4; ni++)
                    mma16816(acc[mi][ni], ar[mi],
                             br[ni >> 1][(ni & 1) * 2], br[ni >> 1][(ni & 1) * 2 + 1]);
        }
    };

    issue(0);
    issue(1);
    issue(2);

    for (int t = 0; t < T; t++) {
        const int ti = t + 3;
        if (ti < T) {
            const int s3 = ti % 5;
            if (ti >= 5) mbar_wait(sb + 40 + s3 * 8, ((ti / 5) - 1) & 1);  // empty[s3]
            issue(ti);
        }
        mbar_wait(sb + (t % 5) * 8, (t / 5) & 1);                          // full[t%5]
        compute(t, sb + 40 + (t % 5) * 8);
    }

    // ---- epilogue: direct register -> global, fused bias (+ sigmoid blend)
    const int lane4 = lane >> 2;
    const int lanec = (lane & 3) * 2;
#pragma unroll
    for (int mi = 0; mi < 4; mi++) {
#pragma unroll
        for (int hf = 0; hf < 2; hf++) {
            const int r = bm + wm + mi * 16 + lane4 + hf * 8;
            const size_t rowE = (size_t)r * EDIM;
#pragma unroll
            for (int ni = 0; ni < 4; ni++) {
                const int c = bn + wn + ni * 8 + lanec;
                float v0 = acc[mi][ni][hf * 2 + 0];
                float v1 = acc[mi][ni][hf * 2 + 1];
                if (g.bias) {
                    float2 bb = *(const float2*)(g.bias + c);
                    v0 += bb.x; v1 += bb.y;
                }
                if (GATE) {
                    __half2 xh = *(const __half2*)(g.X + rowE + c);
                    __half2 ch = *(const __half2*)(g.Xc + rowE + c);
                    float x0 = __low2float(xh), x1 = __high2float(xh);
                    float c0 = __low2float(ch), c1 = __high2float(ch);
                    float s0 = 1.f / (1.f + __expf(-v0));
                    float s1 = 1.f / (1.f + __expf(-v1));
                    float2 o;
                    o.x = s0 * x0 + (1.f - s0) * c0;
                    o.y = s1 * x1 + (1.f - s1) * c1;
                    *(float2*)(g.Cf + rowE + c) = o;
                } else {
                    *(__half2*)(g.Ch + rowE + c) = __floats2half2_rn(v0, v1);
                }
            }
        }
    }
}

// ---------------- fused fp32 -> fp16 conversion (all 7 tensors, one launch) ----------------
#define N4_TEXT ((size_t)BSZ * TDIM / 4)
#define N4_AUD  ((size_t)BSZ * EDIM / 4)
#define N4_WT   ((size_t)EDIM * TDIM / 4)
#define N4_WA   ((size_t)EDIM * EDIM / 4)
#define N4_WG   ((size_t)EDIM * 2 * EDIM / 4)
#define C0 (N4_TEXT)
#define C1 (C0 + N4_AUD)
#define C2 (C1 + N4_WT)
#define C3 (C2 + N4_WA)
#define C4 (C3 + N4_WG)
#define C5 (C4 + N4_WG)
#define C6 (C5 + N4_WA)

struct CvtArgs {
    const float* s0; const float* s1; const float* s2; const float* s3;
    const float* s4; const float* s5; const float* s6;
    __half *d0, *d1, *d2, *d3, *d4, *d5, *d6;
};

__global__ void cvt_all_kernel(CvtArgs a) {
    size_t i = (size_t)blockIdx.x * blockDim.x + threadIdx.x;
    if (i >= C6) return;
    const float* src; __half* dst; size_t off;
    if      (i < C0) { src = a.s0; dst = a.d0; off = i; }
    else if (i < C1) { src = a.s1; dst = a.d1; off = i - C0; }
    else if (i < C2) { src = a.s2; dst = a.d2; off = i - C1; }
    else if (i < C3) { src = a.s3; dst = a.d3; off = i - C2; }
    else if (i < C4) { src = a.s4; dst = a.d4; off = i - C3; }
    else if (i < C5) { src = a.s5; dst = a.d5; off = i - C4; }
    else             { src = a.s6; dst = a.d6; off = i - C5; }
    float4 v = ((const float4*)src)[off];
    __half2 h0 = __floats2half2_rn(v.x, v.y);
    __half2 h1 = __floats2half2_rn(v.z, v.w);
    uint2 u; u.x = *(uint32_t*)&h0; u.y = *(uint32_t*)&h1;
    ((uint2*)dst)[off] = u;
}

__global__ void transpose_cvt1024(const float* __restrict__ in, __half* __restrict__ out) {
    __shared__ float tile[32][33];
    int x = blockIdx.x * 32 + threadIdx.x;
    int y = blockIdx.y * 32 + threadIdx.y;
#pragma unroll
    for (int i = 0; i < 32; i += 8)
        tile[threadIdx.y + i][threadIdx.x] = in[(size_t)(y + i) * EDIM + x];
    __syncthreads();
    x = blockIdx.y * 32 + threadIdx.x;
    y = blockIdx.x * 32 + threadIdx.y;
#pragma unroll
    for (int i = 0; i < 32; i += 8)
        out[(size_t)(y + i) * EDIM + x] = __float2half_rn(tile[threadIdx.x][threadIdx.y + i]);
}

__global__ void bvo_kernel(const float* __restrict__ Wo, const float* __restrict__ bv,
                           const float* __restrict__ bo, float* __restrict__ bvo) {
    int n = blockIdx.x * (blockDim.x >> 5) + (threadIdx.x >> 5);
    int lane = threadIdx.x & 31;
    const float* row = Wo + (size_t)n * EDIM;
    float s = 0.f;
    for (int k = lane; k < EDIM; k += 32) s += row[k] * bv[k];
#pragma unroll
    for (int off = 16; off; off >>= 1) s += __shfl_xor_sync(0xFFFFFFFFu, s, off);
    if (lane == 0) bvo[n] = s + bo[n];
}

// ---------------- launch ----------------
extern "C" void kernel_launch(void* const* d_in, const int* in_sizes, int n_in,
                              void* d_out, int out_size)
{
    const float* text  = (const float*)d_in[0];
    const float* audio = (const float*)d_in[1];
    const float* Wt  = (const float*)d_in[2];
    const float* bt  = (const float*)d_in[3];
    const float* Wa  = (const float*)d_in[4];
    const float* ba  = (const float*)d_in[5];
    // d_in[6..9] = Wq,bq,Wk,bk : dead (softmax over length-1 kv axis == 1 -> ctx == v)
    const float* Wv  = (const float*)d_in[10];
    const float* bv  = (const float*)d_in[11];
    const float* Wo  = (const float*)d_in[12];
    const float* bo  = (const float*)d_in[13];
    const float* Wgt = (const float*)d_in[14];
    const float* bgt = (const float*)d_in[15];
    const float* Wga = (const float*)d_in[16];
    const float* bga = (const float*)d_in[17];
    float* out = (float*)d_out;

    float *bvo;
    __half *t_h, *a_h, *tctx_h, *actx_h, *text_h, *aud_h;
    __half *Wt_h, *Wa_h, *Wgt_h, *Wga_h, *Wo_h, *WvT_h, *Wvo_h;
    cudaGetSymbolAddress((void**)&t_h, g_t_h);       cudaGetSymbolAddress((void**)&a_h, g_a_h);
    cudaGetSymbolAddress((void**)&tctx_h, g_tctx_h); cudaGetSymbolAddress((void**)&actx_h, g_actx_h);
    cudaGetSymbolAddress((void**)&text_h, g_text_h); cudaGetSymbolAddress((void**)&aud_h, g_aud_h);
    cudaGetSymbolAddress((void**)&Wt_h, g_Wt_h);     cudaGetSymbolAddress((void**)&Wa_h, g_Wa_h);
    cudaGetSymbolAddress((void**)&Wgt_h, g_Wgt_h);   cudaGetSymbolAddress((void**)&Wga_h, g_Wga_h);
    cudaGetSymbolAddress((void**)&Wo_h, g_Wo_h);     cudaGetSymbolAddress((void**)&WvT_h, g_WvT_h);
    cudaGetSymbolAddress((void**)&Wvo_h, g_Wvo_h);   cudaGetSymbolAddress((void**)&bvo, g_bvo);

    cudaFuncSetAttribute(hgemm<false, true>,  cudaFuncAttributeMaxDynamicSharedMemorySize, SMEM_BYTES);
    cudaFuncSetAttribute(hgemm<false, false>, cudaFuncAttributeMaxDynamicSharedMemorySize, SMEM_BYTES);
    cudaFuncSetAttribute(hgemm<true, false>,  cudaFuncAttributeMaxDynamicSharedMemorySize, SMEM_BYTES);

    // fused fp16 operand prep (one launch for all 7 tensors)
    {
        CvtArgs ca = { text, audio, Wt, Wa, Wgt, Wga, Wo,
                       text_h, aud_h, Wt_h, Wa_h, Wgt_h, Wga_h, Wo_h };
        cvt_all_kernel<<<(unsigned)((C6 + 255) / 256), 256>>>(ca);
    }
    transpose_cvt1024<<<dim3(32, 32), dim3(32, 8)>>>(Wv, WvT_h);
    bvo_kernel<<<EDIM / 8, 256>>>(Wo, bv, bo, bvo);

    const dim3 blk(256);

    // projections + Wvo in one launch:
    //   z=0: t = text@Wt^T + bt ; z=1: a = audio@Wa^T + ba ; z=2 (y<8): Wvo = Wo@Wv
    {
        GArgs gt  = { text_h, text_h, Wt_h, bt, nullptr, t_h, nullptr, nullptr,
                      TDIM, TDIM, TDIM, TDIM };
        GArgs gaa = { aud_h, aud_h, Wa_h, ba, nullptr, a_h, nullptr, nullptr,
                      EDIM, EDIM, EDIM, EDIM };
        GArgs gw  = { Wo_h, Wo_h, WvT_h, nullptr, nullptr, Wvo_h, nullptr, nullptr,
                      EDIM, EDIM, EDIM, EDIM };
        hgemm<false, true><<<dim3(8, 128, 3), blk, SMEM_BYTES>>>(gt, gaa, gw);
    }
    // contexts (attention collapsed to V-then-O): tctx = a@Wvo^T + bvo ; actx = t@Wvo^T + bvo
    {
        GArgs g0 = { a_h, a_h, Wvo_h, bvo, nullptr, tctx_h, nullptr, nullptr,
                     EDIM, EDIM, EDIM, EDIM };
        GArgs g1 = { t_h, t_h, Wvo_h, bvo, nullptr, actx_h, nullptr, nullptr,
                     EDIM, EDIM, EDIM, EDIM };
        hgemm<false, false><<<dim3(8, 128, 2), blk, SMEM_BYTES>>>(g0, g1, g0);
    }
    // gates: K = 2048, A switches x -> ctx at k = 1024; fused sigmoid blend
    {
        GArgs g0 = { t_h, tctx_h, Wgt_h, bgt, out, nullptr, t_h, tctx_h,
                     EDIM, 2 * EDIM, 2 * EDIM, EDIM };
        GArgs g1 = { a_h, actx_h, Wga_h, bga, out + (size_t)BSZ * EDIM, nullptr, a_h, actx_h,
                     EDIM, 2 * EDIM, 2 * EDIM, EDIM };
        hgemm<true, false><<<dim3(8, 128, 2), blk, SMEM_BYTES>>>(g0, g1, g0);
    }
}

// round 15
// speedup vs baseline: 1.4478x; 1.0044x over previous
#include <cuda_runtime.h>
#include <cuda_fp16.h>
#include <cstdint>

#define BSZ 16384
#define EDIM 1024
#define TDIM 768

// ---------------- scratch (__device__ globals; allocation is forbidden) ----------------
__device__ __half g_t_h[(size_t)BSZ * EDIM];
__device__ __half g_a_h[(size_t)BSZ * EDIM];
__device__ __half g_tctx_h[(size_t)BSZ * EDIM];
__device__ __half g_actx_h[(size_t)BSZ * EDIM];
__device__ __half g_text_h[(size_t)BSZ * TDIM];
__device__ __half g_aud_h[(size_t)BSZ * EDIM];
__device__ __half g_Wt_h[(size_t)EDIM * TDIM];
__device__ __half g_Wa_h[(size_t)EDIM * EDIM];
__device__ __half g_Wgt_h[(size_t)EDIM * 2 * EDIM];
__device__ __half g_Wga_h[(size_t)EDIM * 2 * EDIM];
__device__ __half g_Wo_h[(size_t)EDIM * EDIM];
__device__ __half g_WvT_h[(size_t)EDIM * EDIM];
__device__ __half g_Wvo_h[(size_t)EDIM * EDIM];
__device__ float g_bvo[EDIM];

// ---------------- helpers ----------------
static __device__ __forceinline__ uint32_t s2u(const void* p) {
    uint32_t a;
    asm("{ .reg .u64 t; cvta.to.shared.u64 t, %1; cvt.u32.u64 %0, t; }" : "=r"(a) : "l"(p));
    return a;
}
static __device__ __forceinline__ void cpa16(uint32_t d, const void* s) {
    asm volatile("cp.async.cg.shared.global [%0], [%1], 16;" :: "r"(d), "l"(s));
}
static __device__ __forceinline__ void ldsm4(uint32_t* r, uint32_t addr) {
    asm volatile("ldmatrix.sync.aligned.m8n8.x4.shared.b16 {%0,%1,%2,%3}, [%4];"
                 : "=r"(r[0]), "=r"(r[1]), "=r"(r[2]), "=r"(r[3]) : "r"(addr));
}
static __device__ __forceinline__ void mma16816(float* c, const uint32_t* a, uint32_t b0, uint32_t b1) {
    asm volatile(
        "mma.sync.aligned.m16n8k16.row.col.f32.f16.f16.f32 "
        "{%0,%1,%2,%3}, {%4,%5,%6,%7}, {%8,%9}, {%0,%1,%2,%3};"
        : "+f"(c[0]), "+f"(c[1]), "+f"(c[2]), "+f"(c[3])
        : "r"(a[0]), "r"(a[1]), "r"(a[2]), "r"(a[3]), "r"(b0), "r"(b1));
}
// ---- mbarrier primitives (plain sm_90 PTX; no arch-suffix features) ----
static __device__ __forceinline__ void mbar_init(uint32_t a, uint32_t cnt) {
    asm volatile("mbarrier.init.shared.b64 [%0], %1;" :: "r"(a), "r"(cnt) : "memory");
}
static __device__ __forceinline__ void mbar_arrive(uint32_t a) {
    asm volatile("mbarrier.arrive.shared.b64 _, [%0];" :: "r"(a) : "memory");
}
static __device__ __forceinline__ void cpa_mbar_arrive(uint32_t a) {
    asm volatile("cp.async.mbarrier.arrive.noinc.shared.b64 [%0];" :: "r"(a) : "memory");
}
static __device__ __forceinline__ void mbar_wait(uint32_t a, uint32_t parity) {
    asm volatile(
        "{\n\t.reg .pred P1;\n\t"
        "LAB_%=:\n\t"
        "mbarrier.try_wait.parity.acquire.cta.shared::cta.b64 P1, [%0], %1, 0x989680;\n\t"
        "@P1 bra.uni DONE_%=;\n\t"
        "bra.uni LAB_%=;\n\t"
        "DONE_%=:\n\t}"
        :: "r"(a), "r"(parity) : "memory");
}

// ---------------- SMEM layout ----------------
// [0..40)    full[5] mbarriers  (256 arrivals: every thread's cp-async tracked arrive)
// [40..80)   empty[5] mbarriers (8 arrivals: lane 0 of each warp)
// [1024..)   5 stages x 20480 B (A 128x80 + B 128x80, 80 B row pad = conflict-free ldmatrix)
// Total 103424 B/CTA; 2 CTAs/SM = 206848 <= 228 KB.
// mbarrier ring, issue distance 3, loads balanced across all 256 threads.
// Warp-phase stagger: odd warps consume chunks in order ks=1,0 (both chunks are
// covered by the same full barrier) so ldsm bursts of half the warps overlap the
// mma bursts of the other half instead of phase-alternating on the crossbar.
#define A_BYTES 10240
#define STAGE_BYTES 20480
#define SM_STAGE0 1024
#define SMEM_BYTES (1024 + 5 * STAGE_BYTES)

struct GArgs {
    const __half* A0; const __half* A1; const __half* W;
    const float* bias; float* Cf; __half* Ch;
    const __half* X; const __half* Xc;
    int lda, ldw, K, Ksplit;
};

// C[row, col] = sum_k A[row, k] * W[col, k] (+ bias[col]); A switches A0->A1 at
// k = Ksplit (concat-free gate). GATE: fused sigmoid blend -> Cf (f32).
// !GATE: emits Ch (f16) only.  SMALLZ2: z == 2 lane only covers blockIdx.y < 8
// (the 1024x1024 Wvo GEMM piggybacking on the projections launch).
template <bool GATE, bool SMALLZ2>
__global__ __launch_bounds__(256, 2) void hgemm(GArgs ga, GArgs gb, GArgs gc)
{
    if (SMALLZ2 && blockIdx.z == 2 && blockIdx.y >= 8) return;
    const GArgs g = (blockIdx.z == 0) ? ga : (blockIdx.z == 1 ? gb : gc);
    extern __shared__ __align__(16) char smem[];
    const uint32_t sb = s2u(smem);
    const int tid  = threadIdx.x;
    const int warp = tid >> 5;
    const int lane = tid & 31;
    const int bm = blockIdx.y * 128;
    const int bn = blockIdx.x * 128;
    const int wm = (warp & 1) * 64;    // warp grid 2(m) x 4(n), warp tile 64x32
    const int wn = (warp >> 1) * 32;
    const int T = g.K / 32;
    const int kphase = warp & 1;       // chunk-order stagger within the stage

    const int rowL = tid >> 1;
    const int cL = (tid & 1) * 2;      // 16B units

    if (tid == 0) {
#pragma unroll
        for (int s = 0; s < 5; s++) {
            mbar_init(sb + s * 8, 256);        // full[s]: all-thread cp-async arrivals
            mbar_init(sb + 40 + s * 8, 8);     // empty[s]: lane-0-per-warp arrivals
        }
    }
    __syncthreads();

    auto issue = [&](int ti) {
        const int s = ti % 5;
        const int k0 = ti * 32;
        const __half* Ap; int kk;
        if (k0 < g.Ksplit) { Ap = g.A0; kk = k0; }
        else               { Ap = g.A1; kk = k0 - g.Ksplit; }
        const __half* srcA = Ap + (size_t)(bm + rowL) * g.lda + kk + cL * 8;
        const uint32_t dA = sb + SM_STAGE0 + s * STAGE_BYTES + rowL * 80 + cL * 16;
        cpa16(dA, srcA); cpa16(dA + 16, srcA + 8);
        const __half* srcB = g.W + (size_t)(bn + rowL) * g.ldw + k0 + cL * 8;
        const uint32_t dB = sb + SM_STAGE0 + s * STAGE_BYTES + A_BYTES + rowL * 80 + cL * 16;
        cpa16(dB, srcB); cpa16(dB + 16, srcB + 8);
        cpa_mbar_arrive(sb + s * 8);           // arrive full[s] when these loads land
    };

    const uint32_t aoff = (uint32_t)(wm + (lane & 15)) * 80 + (lane >> 4) * 16;
    const uint32_t boff = (uint32_t)(wn + ((lane >> 4) & 1) * 8 + (lane & 7)) * 80 +
                          ((lane >> 3) & 1) * 16;

    float acc[4][4][4];
#pragma unroll
    for (int i = 0; i < 4; i++)
#pragma unroll
        for (int j = 0; j < 4; j++)
#pragma unroll
            for (int q = 0; q < 4; q++) acc[i][j][q] = 0.f;

    // compute(t): warps consume the two k-chunks in warp-parity order; empty
    // arrive fires once this warp's second chunk is in registers.
    auto compute = [&](int ti, uint32_t emptyAddr) {
        const uint32_t sA = sb + SM_STAGE0 + (ti % 5) * STAGE_BYTES;
        const uint32_t sB = sA + A_BYTES;
#pragma unroll
        for (int kx = 0; kx < 2; kx++) {
            const int ks = kx ^ kphase;
            uint32_t ar[4][4], br[2][4];
#pragma unroll
            for (int mi = 0; mi < 4; mi++)
                ldsm4(ar[mi], sA + aoff + mi * (16 * 80) + ks * 32);
#pragma unroll
            for (int nj = 0; nj < 2; nj++)
                ldsm4(br[nj], sB + boff + nj * (16 * 80) + ks * 32);
            if (kx == 1 && lane == 0) mbar_arrive(emptyAddr);  // stage consumed by this warp
#pragma unroll
            for (int mi = 0; mi < 4; mi++)
#pragma unroll
                for (int ni = 0; ni < 4; ni++)
                    mma16816(acc[mi][ni], ar[mi],
                             br[ni >> 1][(ni & 1) * 2], br[ni >> 1][(ni & 1) * 2 + 1]);
        }
    };

    issue(0);
    issue(1);
    issue(2);

    for (int t = 0; t < T; t++) {
        const int ti = t + 3;
        if (ti < T) {
            const int s3 = ti % 5;
            if (ti >= 5) mbar_wait(sb + 40 + s3 * 8, ((ti / 5) - 1) & 1);  // empty[s3]
            issue(ti);
        }
        mbar_wait(sb + (t % 5) * 8, (t / 5) & 1);                          // full[t%5]
        compute(t, sb + 40 + (t % 5) * 8);
    }

    // ---- epilogue: direct register -> global, fused bias (+ sigmoid blend)
    const int lane4 = lane >> 2;
    const int lanec = (lane & 3) * 2;
#pragma unroll
    for (int mi = 0; mi < 4; mi++) {
#pragma unroll
        for (int hf = 0; hf < 2; hf++) {
            const int r = bm + wm + mi * 16 + lane4 + hf * 8;
            const size_t rowE = (size_t)r * EDIM;
#pragma unroll
            for (int ni = 0; ni < 4; ni++) {
                const int c = bn + wn + ni * 8 + lanec;
                float v0 = acc[mi][ni][hf * 2 + 0];
                float v1 = acc[mi][ni][hf * 2 + 1];
                if (g.bias) {
                    float2 bb = *(const float2*)(g.bias + c);
                    v0 += bb.x; v1 += bb.y;
                }
                if (GATE) {
                    __half2 xh = *(const __half2*)(g.X + rowE + c);
                    __half2 ch = *(const __half2*)(g.Xc + rowE + c);
                    float x0 = __low2float(xh), x1 = __high2float(xh);
                    float c0 = __low2float(ch), c1 = __high2float(ch);
                    float s0 = 1.f / (1.f + __expf(-v0));
                    float s1 = 1.f / (1.f + __expf(-v1));
                    float2 o;
                    o.x = s0 * x0 + (1.f - s0) * c0;
                    o.y = s1 * x1 + (1.f - s1) * c1;
                    *(float2*)(g.Cf + rowE + c) = o;
                } else {
                    *(__half2*)(g.Ch + rowE + c) = __floats2half2_rn(v0, v1);
                }
            }
        }
    }
}

// ---------------- fused fp32 -> fp16 conversion (all 7 tensors, one launch) ----------------
#define N4_TEXT ((size_t)BSZ * TDIM / 4)
#define N4_AUD  ((size_t)BSZ * EDIM / 4)
#define N4_WT   ((size_t)EDIM * TDIM / 4)
#define N4_WA   ((size_t)EDIM * EDIM / 4)
#define N4_WG   ((size_t)EDIM * 2 * EDIM / 4)
#define C0 (N4_TEXT)
#define C1 (C0 + N4_AUD)
#define C2 (C1 + N4_WT)
#define C3 (C2 + N4_WA)
#define C4 (C3 + N4_WG)
#define C5 (C4 + N4_WG)
#define C6 (C5 + N4_WA)

struct CvtArgs {
    const float* s0; const float* s1; const float* s2; const float* s3;
    const float* s4; const float* s5; const float* s6;
    __half *d0, *d1, *d2, *d3, *d4, *d5, *d6;
};

__global__ void cvt_all_kernel(CvtArgs a) {
    size_t i = (size_t)blockIdx.x * blockDim.x + threadIdx.x;
    if (i >= C6) return;
    const float* src; __half* dst; size_t off;
    if      (i < C0) { src = a.s0; dst = a.d0; off = i; }
    else if (i < C1) { src = a.s1; dst = a.d1; off = i - C0; }
    else if (i < C2) { src = a.s2; dst = a.d2; off = i - C1; }
    else if (i < C3) { src = a.s3; dst = a.d3; off = i - C2; }
    else if (i < C4) { src = a.s4; dst = a.d4; off = i - C3; }
    else if (i < C5) { src = a.s5; dst = a.d5; off = i - C4; }
    else             { src = a.s6; dst = a.d6; off = i - C5; }
    float4 v = ((const float4*)src)[off];
    __half2 h0 = __floats2half2_rn(v.x, v.y);
    __half2 h1 = __floats2half2_rn(v.z, v.w);
    uint2 u; u.x = *(uint32_t*)&h0; u.y = *(uint32_t*)&h1;
    ((uint2*)dst)[off] = u;
}

__global__ void transpose_cvt1024(const float* __restrict__ in, __half* __restrict__ out) {
    __shared__ float tile[32][33];
    int x = blockIdx.x * 32 + threadIdx.x;
    int y = blockIdx.y * 32 + threadIdx.y;
#pragma unroll
    for (int i = 0; i < 32; i += 8)
        tile[threadIdx.y + i][threadIdx.x] = in[(size_t)(y + i) * EDIM + x];
    __syncthreads();
    x = blockIdx.y * 32 + threadIdx.x;
    y = blockIdx.x * 32 + threadIdx.y;
#pragma unroll
    for (int i = 0; i < 32; i += 8)
        out[(size_t)(y + i) * EDIM + x] = __float2half_rn(tile[threadIdx.x][threadIdx.y + i]);
}

__global__ void bvo_kernel(const float* __restrict__ Wo, const float* __restrict__ bv,
                           const float* __restrict__ bo, float* __restrict__ bvo) {
    int n = blockIdx.x * (blockDim.x >> 5) + (threadIdx.x >> 5);
    int lane = threadIdx.x & 31;
    const float* row = Wo + (size_t)n * EDIM;
    float s = 0.f;
    for (int k = lane; k < EDIM; k += 32) s += row[k] * bv[k];
#pragma unroll
    for (int off = 16; off; off >>= 1) s += __shfl_xor_sync(0xFFFFFFFFu, s, off);
    if (lane == 0) bvo[n] = s + bo[n];
}

// ---------------- launch ----------------
extern "C" void kernel_launch(void* const* d_in, const int* in_sizes, int n_in,
                              void* d_out, int out_size)
{
    const float* text  = (const float*)d_in[0];
    const float* audio = (const float*)d_in[1];
    const float* Wt  = (const float*)d_in[2];
    const float* bt  = (const float*)d_in[3];
    const float* Wa  = (const float*)d_in[4];
    const float* ba  = (const float*)d_in[5];
    // d_in[6..9] = Wq,bq,Wk,bk : dead (softmax over length-1 kv axis == 1 -> ctx == v)
    const float* Wv  = (const float*)d_in[10];
    const float* bv  = (const float*)d_in[11];
    const float* Wo  = (const float*)d_in[12];
    const float* bo  = (const float*)d_in[13];
    const float* Wgt = (const float*)d_in[14];
    const float* bgt = (const float*)d_in[15];
    const float* Wga = (const float*)d_in[16];
    const float* bga = (const float*)d_in[17];
    float* out = (float*)d_out;

    float *bvo;
    __half *t_h, *a_h, *tctx_h, *actx_h, *text_h, *aud_h;
    __half *Wt_h, *Wa_h, *Wgt_h, *Wga_h, *Wo_h, *WvT_h, *Wvo_h;
    cudaGetSymbolAddress((void**)&t_h, g_t_h);       cudaGetSymbolAddress((void**)&a_h, g_a_h);
    cudaGetSymbolAddress((void**)&tctx_h, g_tctx_h); cudaGetSymbolAddress((void**)&actx_h, g_actx_h);
    cudaGetSymbolAddress((void**)&text_h, g_text_h); cudaGetSymbolAddress((void**)&aud_h, g_aud_h);
    cudaGetSymbolAddress((void**)&Wt_h, g_Wt_h);     cudaGetSymbolAddress((void**)&Wa_h, g_Wa_h);
    cudaGetSymbolAddress((void**)&Wgt_h, g_Wgt_h);   cudaGetSymbolAddress((void**)&Wga_h, g_Wga_h);
    cudaGetSymbolAddress((void**)&Wo_h, g_Wo_h);     cudaGetSymbolAddress((void**)&WvT_h, g_WvT_h);
    cudaGetSymbolAddress((void**)&Wvo_h, g_Wvo_h);   cudaGetSymbolAddress((void**)&bvo, g_bvo);

    cudaFuncSetAttribute(hgemm<false, true>,  cudaFuncAttributeMaxDynamicSharedMemorySize, SMEM_BYTES);
    cudaFuncSetAttribute(hgemm<false, false>, cudaFuncAttributeMaxDynamicSharedMemorySize, SMEM_BYTES);
    cudaFuncSetAttribute(hgemm<true, false>,  cudaFuncAttributeMaxDynamicSharedMemorySize, SMEM_BYTES);

    // fused fp16 operand prep (one launch for all 7 tensors)
    {
        CvtArgs ca = { text, audio, Wt, Wa, Wgt, Wga, Wo,
                       text_h, aud_h, Wt_h, Wa_h, Wgt_h, Wga_h, Wo_h };
        cvt_all_kernel<<<(unsigned)((C6 + 255) / 256), 256>>>(ca);
    }
    transpose_cvt1024<<<dim3(32, 32), dim3(32, 8)>>>(Wv, WvT_h);
    bvo_kernel<<<EDIM / 8, 256>>>(Wo, bv, bo, bvo);

    const dim3 blk(256);

    // projections + Wvo in one launch:
    //   z=0: t = text@Wt^T + bt ; z=1: a = audio@Wa^T + ba ; z=2 (y<8): Wvo = Wo@Wv
    {
        GArgs gt  = { text_h, text_h, Wt_h, bt, nullptr, t_h, nullptr, nullptr,
                      TDIM, TDIM, TDIM, TDIM };
        GArgs gaa = { aud_h, aud_h, Wa_h, ba, nullptr, a_h, nullptr, nullptr,
                      EDIM, EDIM, EDIM, EDIM };
        GArgs gw  = { Wo_h, Wo_h, WvT_h, nullptr, nullptr, Wvo_h, nullptr, nullptr,
                      EDIM, EDIM, EDIM, EDIM };
        hgemm<false, true><<<dim3(8, 128, 3), blk, SMEM_BYTES>>>(gt, gaa, gw);
    }
    // contexts (attention collapsed to V-then-O): tctx = a@Wvo^T + bvo ; actx = t@Wvo^T + bvo
    {
        GArgs g0 = { a_h, a_h, Wvo_h, bvo, nullptr, tctx_h, nullptr, nullptr,
                     EDIM, EDIM, EDIM, EDIM };
        GArgs g1 = { t_h, t_h, Wvo_h, bvo, nullptr, actx_h, nullptr, nullptr,
                     EDIM, EDIM, EDIM, EDIM };
        hgemm<false, false><<<dim3(8, 128, 2), blk, SMEM_BYTES>>>(g0, g1, g0);
    }
    // gates: K = 2048, A switches x -> ctx at k = 1024; fused sigmoid blend
    {
        GArgs g0 = { t_h, tctx_h, Wgt_h, bgt, out, nullptr, t_h, tctx_h,
                     EDIM, 2 * EDIM, 2 * EDIM, EDIM };
        GArgs g1 = { a_h, actx_h, Wga_h, bga, out + (size_t)BSZ * EDIM, nullptr, a_h, actx_h,
                     EDIM, 2 * EDIM, 2 * EDIM, EDIM };
        hgemm<true, false><<<dim3(8, 128, 2), blk, SMEM_BYTES>>>(g0, g1, g0);
    }
}

// round 16
// speedup vs baseline: 1.4973x; 1.0342x over previous
#include <cuda_runtime.h>
#include <cuda_fp16.h>
#include <cstdint>

#define BSZ 16384
#define EDIM 1024
#define TDIM 768

// ---------------- scratch (__device__ globals; allocation is forbidden) ----------------
__device__ __half g_t_h[(size_t)BSZ * EDIM];
__device__ __half g_a_h[(size_t)BSZ * EDIM];
__device__ __half g_tctx_h[(size_t)BSZ * EDIM];
__device__ __half g_actx_h[(size_t)BSZ * EDIM];
__device__ __half g_text_h[(size_t)BSZ * TDIM];
__device__ __half g_aud_h[(size_t)BSZ * EDIM];
__device__ __half g_Wt_h[(size_t)EDIM * TDIM];
__device__ __half g_Wa_h[(size_t)EDIM * EDIM];
__device__ __half g_Wgt_h[(size_t)EDIM * 2 * EDIM];
__device__ __half g_Wga_h[(size_t)EDIM * 2 * EDIM];
__device__ __half g_Wo_h[(size_t)EDIM * EDIM];
__device__ __half g_WvT_h[(size_t)EDIM * EDIM];
__device__ __half g_Wvo_h[(size_t)EDIM * EDIM];
__device__ float g_bvo[EDIM];

// ---------------- helpers ----------------
static __device__ __forceinline__ uint32_t s2u(const void* p) {
    uint32_t a;
    asm("{ .reg .u64 t; cvta.to.shared.u64 t, %1; cvt.u32.u64 %0, t; }" : "=r"(a) : "l"(p));
    return a;
}
static __device__ __forceinline__ void cpa16(uint32_t d, const void* s) {
    asm volatile("cp.async.cg.shared.global [%0], [%1], 16;" :: "r"(d), "l"(s));
}
static __device__ __forceinline__ void ldsm4(uint32_t* r, uint32_t addr) {
    asm volatile("ldmatrix.sync.aligned.m8n8.x4.shared.b16 {%0,%1,%2,%3}, [%4];"
                 : "=r"(r[0]), "=r"(r[1]), "=r"(r[2]), "=r"(r[3]) : "r"(addr));
}
static __device__ __forceinline__ void mma16816(float* c, const uint32_t* a, uint32_t b0, uint32_t b1) {
    asm volatile(
        "mma.sync.aligned.m16n8k16.row.col.f32.f16.f16.f32 "
        "{%0,%1,%2,%3}, {%4,%5,%6,%7}, {%8,%9}, {%0,%1,%2,%3};"
        : "+f"(c[0]), "+f"(c[1]), "+f"(c[2]), "+f"(c[3])
        : "r"(a[0]), "r"(a[1]), "r"(a[2]), "r"(a[3]), "r"(b0), "r"(b1));
}
// ---- mbarrier primitives (plain sm_90 PTX; no arch-suffix features) ----
static __device__ __forceinline__ void mbar_init(uint32_t a, uint32_t cnt) {
    asm volatile("mbarrier.init.shared.b64 [%0], %1;" :: "r"(a), "r"(cnt) : "memory");
}
static __device__ __forceinline__ void mbar_arrive(uint32_t a) {
    asm volatile("mbarrier.arrive.shared.b64 _, [%0];" :: "r"(a) : "memory");
}
static __device__ __forceinline__ void cpa_mbar_arrive(uint32_t a) {
    asm volatile("cp.async.mbarrier.arrive.noinc.shared.b64 [%0];" :: "r"(a) : "memory");
}
static __device__ __forceinline__ void mbar_wait(uint32_t a, uint32_t parity) {
    asm volatile(
        "{\n\t.reg .pred P1;\n\t"
        "LAB_%=:\n\t"
        "mbarrier.try_wait.parity.acquire.cta.shared::cta.b64 P1, [%0], %1, 0x989680;\n\t"
        "@P1 bra.uni DONE_%=;\n\t"
        "bra.uni LAB_%=;\n\t"
        "DONE_%=:\n\t}"
        :: "r"(a), "r"(parity) : "memory");
}

// ---------------- SMEM layout ----------------
// CTA tile 128(m) x 256(n), K-tile 32, 16 warps (warp grid 2m x 8n, warp tile
// 64x32 unchanged -> same acc/frag register footprint as the 830us kernel).
// [0..40)    full[5] mbarriers  (512 arrivals: every thread's cp-async tracked arrive)
// [40..80)   empty[5] mbarriers (16 arrivals: lane 0 of each warp)
// [1024..)   5 stages x 30720 B (A 128x80 = 10240 B + B 256x80 = 20480 B)
// Total 1024 + 153600 = 154624 B/CTA; 1 CTA/SM (regs: 512 x ~122 = full RF).
// L2-traffic rationale: BN=256 halves A re-reads (x8 -> x4) -> per-GEMM L2 reads
// drop 512 MB -> 384 MB; LDS stays under the 128 B/cyc crossbar (117 B/cyc @ peak).
#define A_BYTES 10240
#define STAGE_BYTES 30720
#define SM_STAGE0 1024
#define SMEM_BYTES (1024 + 5 * STAGE_BYTES)

struct GArgs {
    const __half* A0; const __half* A1; const __half* W;
    const float* bias; float* Cf; __half* Ch;
    const __half* X; const __half* Xc;
    int lda, ldw, K, Ksplit;
};

// C[row, col] = sum_k A[row, k] * W[col, k] (+ bias[col]); A switches A0->A1 at
// k = Ksplit (concat-free gate). GATE: fused sigmoid blend -> Cf (f32).
// !GATE: emits Ch (f16) only.  SMALLZ2: z == 2 lane only covers blockIdx.y < 8
// (the 1024x1024 Wvo GEMM piggybacking on the projections launch).
template <bool GATE, bool SMALLZ2>
__global__ __launch_bounds__(512, 1) void hgemm(GArgs ga, GArgs gb, GArgs gc)
{
    if (SMALLZ2 && blockIdx.z == 2 && blockIdx.y >= 8) return;
    const GArgs g = (blockIdx.z == 0) ? ga : (blockIdx.z == 1 ? gb : gc);
    extern __shared__ __align__(16) char smem[];
    const uint32_t sb = s2u(smem);
    const int tid  = threadIdx.x;
    const int warp = tid >> 5;
    const int lane = tid & 31;
    const int bm = blockIdx.y * 128;
    const int bn = blockIdx.x * 256;
    const int wm = (warp & 1) * 64;    // warp grid 2(m) x 8(n), warp tile 64x32
    const int wn = (warp >> 1) * 32;
    const int T = g.K / 32;
    const int kphase = warp & 1;       // chunk-order stagger within the stage

    const int rowL = tid >> 1;         // 0..255
    const int cL = tid & 1;            // 32B half-row selector

    if (tid == 0) {
#pragma unroll
        for (int s = 0; s < 5; s++) {
            mbar_init(sb + s * 8, 512);        // full[s]: all-thread cp-async arrivals
            mbar_init(sb + 40 + s * 8, 16);    // empty[s]: lane-0-per-warp arrivals
        }
    }
    __syncthreads();

    // Loads: threads 0..255 also load A (row tid/2, 32B half cL); ALL threads
    // load B (row tid/2 of 256, 32B half cL). Every thread ends with a tracked arrive.
    auto issue = [&](int ti) {
        const int s = ti % 5;
        const int k0 = ti * 32;
        if (tid < 256) {
            const __half* Ap; int kk;
            if (k0 < g.Ksplit) { Ap = g.A0; kk = k0; }
            else               { Ap = g.A1; kk = k0 - g.Ksplit; }
            const int rA = tid >> 1;
            const __half* srcA = Ap + (size_t)(bm + rA) * g.lda + kk + cL * 16;
            const uint32_t dA = sb + SM_STAGE0 + s * STAGE_BYTES + rA * 80 + cL * 32;
            cpa16(dA, srcA); cpa16(dA + 16, srcA + 8);
        }
        const __half* srcB = g.W + (size_t)(bn + rowL) * g.ldw + k0 + cL * 16;
        const uint32_t dB = sb + SM_STAGE0 + s * STAGE_BYTES + A_BYTES + rowL * 80 + cL * 32;
        cpa16(dB, srcB); cpa16(dB + 16, srcB + 8);
        cpa_mbar_arrive(sb + s * 8);           // arrive full[s] when this thread's loads land
    };

    const uint32_t aoff = (uint32_t)(wm + (lane & 15)) * 80 + (lane >> 4) * 16;
    const uint32_t boff = (uint32_t)(wn + ((lane >> 4) & 1) * 8 + (lane & 7)) * 80 +
                          ((lane >> 3) & 1) * 16;

    float acc[4][4][4];
#pragma unroll
    for (int i = 0; i < 4; i++)
#pragma unroll
        for (int j = 0; j < 4; j++)
#pragma unroll
            for (int q = 0; q < 4; q++) acc[i][j][q] = 0.f;

    auto compute = [&](int ti, uint32_t emptyAddr) {
        const uint32_t sA = sb + SM_STAGE0 + (ti % 5) * STAGE_BYTES;
        const uint32_t sB = sA + A_BYTES;
#pragma unroll
        for (int kx = 0; kx < 2; kx++) {
            const int ks = kx ^ kphase;
            uint32_t ar[4][4], br[2][4];
#pragma unroll
            for (int mi = 0; mi < 4; mi++)
                ldsm4(ar[mi], sA + aoff + mi * (16 * 80) + ks * 32);
#pragma unroll
            for (int nj = 0; nj < 2; nj++)
                ldsm4(br[nj], sB + boff + nj * (16 * 80) + ks * 32);
            if (kx == 1 && lane == 0) mbar_arrive(emptyAddr);  // stage consumed by this warp
#pragma unroll
            for (int mi = 0; mi < 4; mi++)
#pragma unroll
                for (int ni = 0; ni < 4; ni++)
                    mma16816(acc[mi][ni], ar[mi],
                             br[ni >> 1][(ni & 1) * 2], br[ni >> 1][(ni & 1) * 2 + 1]);
        }
    };

    issue(0);
    issue(1);
    issue(2);

    for (int t = 0; t < T; t++) {
        const int ti = t + 3;
        if (ti < T) {
            const int s3 = ti % 5;
            if (ti >= 5) mbar_wait(sb + 40 + s3 * 8, ((ti / 5) - 1) & 1);  // empty[s3]
            issue(ti);
        }
        mbar_wait(sb + (t % 5) * 8, (t / 5) & 1);                          // full[t%5]
        compute(t, sb + 40 + (t % 5) * 8);
    }

    // ---- epilogue: direct register -> global, fused bias (+ sigmoid blend)
    const int lane4 = lane >> 2;
    const int lanec = (lane & 3) * 2;
#pragma unroll
    for (int mi = 0; mi < 4; mi++) {
#pragma unroll
        for (int hf = 0; hf < 2; hf++) {
            const int r = bm + wm + mi * 16 + lane4 + hf * 8;
            const size_t rowE = (size_t)r * EDIM;
#pragma unroll
            for (int ni = 0; ni < 4; ni++) {
                const int c = bn + wn + ni * 8 + lanec;
                float v0 = acc[mi][ni][hf * 2 + 0];
                float v1 = acc[mi][ni][hf * 2 + 1];
                if (g.bias) {
                    float2 bb = *(const float2*)(g.bias + c);
                    v0 += bb.x; v1 += bb.y;
                }
                if (GATE) {
                    __half2 xh = *(const __half2*)(g.X + rowE + c);
                    __half2 ch = *(const __half2*)(g.Xc + rowE + c);
                    float x0 = __low2float(xh), x1 = __high2float(xh);
                    float c0 = __low2float(ch), c1 = __high2float(ch);
                    float s0 = 1.f / (1.f + __expf(-v0));
                    float s1 = 1.f / (1.f + __expf(-v1));
                    float2 o;
                    o.x = s0 * x0 + (1.f - s0) * c0;
                    o.y = s1 * x1 + (1.f - s1) * c1;
                    *(float2*)(g.Cf + rowE + c) = o;
                } else {
                    *(__half2*)(g.Ch + rowE + c) = __floats2half2_rn(v0, v1);
                }
            }
        }
    }
}

// ---------------- fused fp32 -> fp16 conversion (all 7 tensors, one launch) ----------------
#define N4_TEXT ((size_t)BSZ * TDIM / 4)
#define N4_AUD  ((size_t)BSZ * EDIM / 4)
#define N4_WT   ((size_t)EDIM * TDIM / 4)
#define N4_WA   ((size_t)EDIM * EDIM / 4)
#define N4_WG   ((size_t)EDIM * 2 * EDIM / 4)
#define C0 (N4_TEXT)
#define C1 (C0 + N4_AUD)
#define C2 (C1 + N4_WT)
#define C3 (C2 + N4_WA)
#define C4 (C3 + N4_WG)
#define C5 (C4 + N4_WG)
#define C6 (C5 + N4_WA)

struct CvtArgs {
    const float* s0; const float* s1; const float* s2; const float* s3;
    const float* s4; const float* s5; const float* s6;
    __half *d0, *d1, *d2, *d3, *d4, *d5, *d6;
};

__global__ void cvt_all_kernel(CvtArgs a) {
    size_t i = (size_t)blockIdx.x * blockDim.x + threadIdx.x;
    if (i >= C6) return;
    const float* src; __half* dst; size_t off;
    if      (i < C0) { src = a.s0; dst = a.d0; off = i; }
    else if (i < C1) { src = a.s1; dst = a.d1; off = i - C0; }
    else if (i < C2) { src = a.s2; dst = a.d2; off = i - C1; }
    else if (i < C3) { src = a.s3; dst = a.d3; off = i - C2; }
    else if (i < C4) { src = a.s4; dst = a.d4; off = i - C3; }
    else if (i < C5) { src = a.s5; dst = a.d5; off = i - C4; }
    else             { src = a.s6; dst = a.d6; off = i - C5; }
    float4 v = ((const float4*)src)[off];
    __half2 h0 = __floats2half2_rn(v.x, v.y);
    __half2 h1 = __floats2half2_rn(v.z, v.w);
    uint2 u; u.x = *(uint32_t*)&h0; u.y = *(uint32_t*)&h1;
    ((uint2*)dst)[off] = u;
}

__global__ void transpose_cvt1024(const float* __restrict__ in, __half* __restrict__ out) {
    __shared__ float tile[32][33];
    int x = blockIdx.x * 32 + threadIdx.x;
    int y = blockIdx.y * 32 + threadIdx.y;
#pragma unroll
    for (int i = 0; i < 32; i += 8)
        tile[threadIdx.y + i][threadIdx.x] = in[(size_t)(y + i) * EDIM + x];
    __syncthreads();
    x = blockIdx.y * 32 + threadIdx.x;
    y = blockIdx.x * 32 + threadIdx.y;
#pragma unroll
    for (int i = 0; i < 32; i += 8)
        out[(size_t)(y + i) * EDIM + x] = __float2half_rn(tile[threadIdx.x][threadIdx.y + i]);
}

__global__ void bvo_kernel(const float* __restrict__ Wo, const float* __restrict__ bv,
                           const float* __restrict__ bo, float* __restrict__ bvo) {
    int n = blockIdx.x * (blockDim.x >> 5) + (threadIdx.x >> 5);
    int lane = threadIdx.x & 31;
    const float* row = Wo + (size_t)n * EDIM;
    float s = 0.f;
    for (int k = lane; k < EDIM; k += 32) s += row[k] * bv[k];
#pragma unroll
    for (int off = 16; off; off >>= 1) s += __shfl_xor_sync(0xFFFFFFFFu, s, off);
    if (lane == 0) bvo[n] = s + bo[n];
}

// ---------------- launch ----------------
extern "C" void kernel_launch(void* const* d_in, const int* in_sizes, int n_in,
                              void* d_out, int out_size)
{
    const float* text  = (const float*)d_in[0];
    const float* audio = (const float*)d_in[1];
    const float* Wt  = (const float*)d_in[2];
    const float* bt  = (const float*)d_in[3];
    const float* Wa  = (const float*)d_in[4];
    const float* ba  = (const float*)d_in[5];
    // d_in[6..9] = Wq,bq,Wk,bk : dead (softmax over length-1 kv axis == 1 -> ctx == v)
    const float* Wv  = (const float*)d_in[10];
    const float* bv  = (const float*)d_in[11];
    const float* Wo  = (const float*)d_in[12];
    const float* bo  = (const float*)d_in[13];
    const float* Wgt = (const float*)d_in[14];
    const float* bgt = (const float*)d_in[15];
    const float* Wga = (const float*)d_in[16];
    const float* bga = (const float*)d_in[17];
    float* out = (float*)d_out;

    float *bvo;
    __half *t_h, *a_h, *tctx_h, *actx_h, *text_h, *aud_h;
    __half *Wt_h, *Wa_h, *Wgt_h, *Wga_h, *Wo_h, *WvT_h, *Wvo_h;
    cudaGetSymbolAddress((void**)&t_h, g_t_h);       cudaGetSymbolAddress((void**)&a_h, g_a_h);
    cudaGetSymbolAddress((void**)&tctx_h, g_tctx_h); cudaGetSymbolAddress((void**)&actx_h, g_actx_h);
    cudaGetSymbolAddress((void**)&text_h, g_text_h); cudaGetSymbolAddress((void**)&aud_h, g_aud_h);
    cudaGetSymbolAddress((void**)&Wt_h, g_Wt_h);     cudaGetSymbolAddress((void**)&Wa_h, g_Wa_h);
    cudaGetSymbolAddress((void**)&Wgt_h, g_Wgt_h);   cudaGetSymbolAddress((void**)&Wga_h, g_Wga_h);
    cudaGetSymbolAddress((void**)&Wo_h, g_Wo_h);     cudaGetSymbolAddress((void**)&WvT_h, g_WvT_h);
    cudaGetSymbolAddress((void**)&Wvo_h, g_Wvo_h);   cudaGetSymbolAddress((void**)&bvo, g_bvo);

    cudaFuncSetAttribute(hgemm<false, true>,  cudaFuncAttributeMaxDynamicSharedMemorySize, SMEM_BYTES);
    cudaFuncSetAttribute(hgemm<false, false>, cudaFuncAttributeMaxDynamicSharedMemorySize, SMEM_BYTES);
    cudaFuncSetAttribute(hgemm<true, false>,  cudaFuncAttributeMaxDynamicSharedMemorySize, SMEM_BYTES);

    // fused fp16 operand prep (one launch for all 7 tensors)
    {
        CvtArgs ca = { text, audio, Wt, Wa, Wgt, Wga, Wo,
                       text_h, aud_h, Wt_h, Wa_h, Wgt_h, Wga_h, Wo_h };
        cvt_all_kernel<<<(unsigned)((C6 + 255) / 256), 256>>>(ca);
    }
    transpose_cvt1024<<<dim3(32, 32), dim3(32, 8)>>>(Wv, WvT_h);
    bvo_kernel<<<EDIM / 8, 256>>>(Wo, bv, bo, bvo);

    const dim3 blk(512);

    // projections + Wvo in one launch:
    //   z=0: t = text@Wt^T + bt ; z=1: a = audio@Wa^T + ba ; z=2 (y<8): Wvo = Wo@Wv
    {
        GArgs gt  = { text_h, text_h, Wt_h, bt, nullptr, t_h, nullptr, nullptr,
                      TDIM, TDIM, TDIM, TDIM };
        GArgs gaa = { aud_h, aud_h, Wa_h, ba, nullptr, a_h, nullptr, nullptr,
                      EDIM, EDIM, EDIM, EDIM };
        GArgs gw  = { Wo_h, Wo_h, WvT_h, nullptr, nullptr, Wvo_h, nullptr, nullptr,
                      EDIM, EDIM, EDIM, EDIM };
        hgemm<false, true><<<dim3(4, 128, 3), blk, SMEM_BYTES>>>(gt, gaa, gw);
    }
    // contexts (attention collapsed to V-then-O): tctx = a@Wvo^T + bvo ; actx = t@Wvo^T + bvo
    {
        GArgs g0 = { a_h, a_h, Wvo_h, bvo, nullptr, tctx_h, nullptr, nullptr,
                     EDIM, EDIM, EDIM, EDIM };
        GArgs g1 = { t_h, t_h, Wvo_h, bvo, nullptr, actx_h, nullptr, nullptr,
                     EDIM, EDIM, EDIM, EDIM };
        hgemm<false, false><<<dim3(4, 128, 2), blk, SMEM_BYTES>>>(g0, g1, g0);
    }
    // gates: K = 2048, A switches x -> ctx at k = 1024; fused sigmoid blend
    {
        GArgs g0 = { t_h, tctx_h, Wgt_h, bgt, out, nullptr, t_h, tctx_h,
                     EDIM, 2 * EDIM, 2 * EDIM, EDIM };
        GArgs g1 = { a_h, actx_h, Wga_h, bga, out + (size_t)BSZ * EDIM, nullptr, a_h, actx_h,
                     EDIM, 2 * EDIM, 2 * EDIM, EDIM };
        hgemm<true, false><<<dim3(4, 128, 2), blk, SMEM_BYTES>>>(g0, g1, g0);
    }
}